// round 5
// baseline (speedup 1.0000x reference)
#include <cuda_runtime.h>

#define KTAGS 48
#define PF 8
#define L2E 1.4426950408889634f
#define LN2 0.6931471805599453f

__device__ float g_res[4096];

__device__ __forceinline__ unsigned long long pk2(float lo, float hi) {
    unsigned long long r;
    asm("mov.b64 %0,{%1,%2};" : "=l"(r) : "f"(lo), "f"(hi));
    return r;
}
__device__ __forceinline__ void unpk2(unsigned long long v, float& a, float& b) {
    asm("mov.b64 {%0,%1},%2;" : "=f"(a), "=f"(b) : "l"(v));
}
__device__ __forceinline__ unsigned long long ffma2(unsigned long long a, unsigned long long b,
                                                    unsigned long long c) {
    unsigned long long d;
    asm("fma.rn.f32x2 %0,%1,%2,%3;" : "=l"(d) : "l"(a), "l"(b), "l"(c));
    return d;
}
__device__ __forceinline__ unsigned long long fadd2(unsigned long long a, unsigned long long b) {
    unsigned long long d;
    asm("add.rn.f32x2 %0,%1,%2;" : "=l"(d) : "l"(a), "l"(b));
    return d;
}
__device__ __forceinline__ float ex2f(float x) {
    float r; asm("ex2.approx.f32 %0,%1;" : "=f"(r) : "f"(x)); return r;
}
__device__ __forceinline__ float lg2f(float x) {
    float r; asm("lg2.approx.f32 %0,%1;" : "=f"(r) : "f"(x)); return r;
}
__device__ __forceinline__ float rcpf(float x) {
    float r; asm("rcp.approx.f32 %0,%1;" : "=f"(r) : "f"(x)); return r;
}

// Two batch elements per block; thread i owns tag-row i for BOTH chains.
// E = exp(transition) lives once in registers (batch-invariant).
// Linear-domain recursion per chain: w = (E w) * exp(emis) / r, r = w0(stale),
// scale off-chain via C2 += lg2(r). One barrier per fused step serves both
// chains; their LDS/FFMA latency chains overlap.
__global__ void __launch_bounds__(KTAGS) crf_forward(
    const float* __restrict__ emis,   // [B, T, K] f32
    const int* __restrict__ lengths,  // [B] i32
    const int* __restrict__ tags,     // [B, T] i32
    const float* __restrict__ prior,  // [K]
    const float* __restrict__ trans,  // [K, K]  trans[i*K+j] = score(j -> i)
    const float* __restrict__ ftrans, // [K]
    int T)
{
    __shared__ __align__(16) float sv0[2][KTAGS];
    __shared__ __align__(16) float sv1[2][KTAGS];
    __shared__ float red0[KTAGS];
    __shared__ float red1[KTAGS];

    const int i = threadIdx.x;
    const int b0 = 2 * blockIdx.x;
    const int b1 = b0 + 1;

    int L0 = lengths[b0]; L0 = L0 < 1 ? 1 : (L0 > T ? T : L0);
    int L1 = lengths[b1]; L1 = L1 < 1 ? 1 : (L1 > T ? T : L1);
    const int Lmax = L0 > L1 ? L0 : L1;

    const float* eb0 = emis + (size_t)b0 * T * KTAGS;
    const float* eb1 = emis + (size_t)b1 * T * KTAGS;

    // Row i of E = exp(transition[i, :]) packed as 24 f32x2 registers (shared by both chains).
    unsigned long long E[24];
    {
        const float4* tr = (const float4*)(trans + i * KTAGS);
#pragma unroll
        for (int q = 0; q < 12; q++) {
            float4 v = tr[q];
            E[2 * q]     = pk2(ex2f(v.x * L2E), ex2f(v.y * L2E));
            E[2 * q + 1] = pk2(ex2f(v.z * L2E), ex2f(v.w * L2E));
        }
    }

    // Prefetch rings (raw emissions; exp at consume time).
    float raw0[PF], raw1[PF];
#pragma unroll
    for (int d = 0; d < PF; d++) {
        int t = 1 + d;
        raw0[d] = (t < L0) ? eb0[(size_t)t * KTAGS + i] : 0.0f;
        raw1[d] = (t < L1) ? eb1[(size_t)t * KTAGS + i] : 0.0f;
    }

    // t = 0 init for both chains.
    float a00 = eb0[i] + prior[i];
    float a01 = eb1[i] + prior[i];
    red0[i] = a00;
    red1[i] = a01;
    __syncthreads();
    float m0 = red0[0], m1 = red1[0];
    float C20 = m0 * L2E, C21 = m1 * L2E;
    float w0 = ex2f((a00 - m0) * L2E);
    float w1 = ex2f((a01 - m1) * L2E);
    sv0[0][i] = w0;
    sv1[0][i] = w1;
    __syncthreads();
    int p0 = 0, p1 = 0;

    for (int t0 = 1; t0 < Lmax; t0 += PF) {
#pragma unroll
        for (int d = 0; d < PF; d++) {
            const int t = t0 + d;
            if (t >= Lmax) break;

            if (t < L0) {
                float eet = ex2f(raw0[d] * L2E);
                int tn = t + PF;
                raw0[d] = (tn < L0) ? eb0[(size_t)tn * KTAGS + i] : 0.0f;

                float r = sv0[p0][0];
                float g = eet * rcpf(r);
                C20 += lg2f(r);

                const ulonglong2* vv = (const ulonglong2*)sv0[p0];
                unsigned long long a0 = pk2(0.0f, 0.0f), a1 = a0, a2 = a0, a3 = a0;
#pragma unroll
                for (int q = 0; q < 12; q += 2) {
                    ulonglong2 x0 = vv[q];
                    ulonglong2 x1 = vv[q + 1];
                    a0 = ffma2(E[2 * q],     x0.x, a0);
                    a1 = ffma2(E[2 * q + 1], x0.y, a1);
                    a2 = ffma2(E[2 * q + 2], x1.x, a2);
                    a3 = ffma2(E[2 * q + 3], x1.y, a3);
                }
                unsigned long long s2 = fadd2(fadd2(a0, a1), fadd2(a2, a3));
                float slo, shi;
                unpk2(s2, slo, shi);
                w0 = (slo + shi) * g;
                sv0[p0 ^ 1][i] = w0;
            }

            if (t < L1) {
                float eet = ex2f(raw1[d] * L2E);
                int tn = t + PF;
                raw1[d] = (tn < L1) ? eb1[(size_t)tn * KTAGS + i] : 0.0f;

                float r = sv1[p1][0];
                float g = eet * rcpf(r);
                C21 += lg2f(r);

                const ulonglong2* vv = (const ulonglong2*)sv1[p1];
                unsigned long long a0 = pk2(0.0f, 0.0f), a1 = a0, a2 = a0, a3 = a0;
#pragma unroll
                for (int q = 0; q < 12; q += 2) {
                    ulonglong2 x0 = vv[q];
                    ulonglong2 x1 = vv[q + 1];
                    a0 = ffma2(E[2 * q],     x0.x, a0);
                    a1 = ffma2(E[2 * q + 1], x0.y, a1);
                    a2 = ffma2(E[2 * q + 2], x1.x, a2);
                    a3 = ffma2(E[2 * q + 3], x1.y, a3);
                }
                unsigned long long s2 = fadd2(fadd2(a0, a1), fadd2(a2, a3));
                float slo, shi;
                unpk2(s2, slo, shi);
                w1 = (slo + shi) * g;
                sv1[p1 ^ 1][i] = w1;
            }

            __syncthreads();
            if (t < L0) p0 ^= 1;
            if (t < L1) p1 ^= 1;
        }
    }

    // ---- logZ per chain ----
    red0[i] = w0 * ex2f(ftrans[i] * L2E);
    red1[i] = w1 * ex2f(ftrans[i] * L2E);
    __syncthreads();
    float logZ0 = 0.0f, logZ1 = 0.0f;
    if (i == 0) {
        float s0 = 0.0f, s1 = 0.0f;
#pragma unroll
        for (int j = 0; j < KTAGS; j++) { s0 += red0[j]; s1 += red1[j]; }
        logZ0 = (lg2f(s0) + C20) * LN2;
        logZ1 = (lg2f(s1) + C21) * LN2;
    }
    __syncthreads();  // red reused below

    // ---- path scores ----
    const int* tb0 = tags + (size_t)b0 * T;
    const int* tb1 = tags + (size_t)b1 * T;
    float acc0 = 0.0f, acc1 = 0.0f;
    for (int t = i; t < L0; t += KTAGS) {
        int tg = min(max(tb0[t], 0), KTAGS - 1);
        float tr = (t == 0) ? prior[tg]
                            : trans[tg * KTAGS + min(max(tb0[t - 1], 0), KTAGS - 1)];
        acc0 += eb0[(size_t)t * KTAGS + tg] + tr;
    }
    for (int t = i; t < L1; t += KTAGS) {
        int tg = min(max(tb1[t], 0), KTAGS - 1);
        float tr = (t == 0) ? prior[tg]
                            : trans[tg * KTAGS + min(max(tb1[t - 1], 0), KTAGS - 1)];
        acc1 += eb1[(size_t)t * KTAGS + tg] + tr;
    }
    red0[i] = acc0;
    red1[i] = acc1;
    __syncthreads();
    if (i == 0) {
        float ps0 = 0.0f, ps1 = 0.0f;
#pragma unroll
        for (int j = 0; j < KTAGS; j++) { ps0 += red0[j]; ps1 += red1[j]; }
        ps0 += ftrans[min(max(tb0[L0 - 1], 0), KTAGS - 1)];
        ps1 += ftrans[min(max(tb1[L1 - 1], 0), KTAGS - 1)];
        g_res[b0] = logZ0 - ps0;
        g_res[b1] = logZ1 - ps1;
    }
}

__global__ void crf_reduce(float* __restrict__ out, int B) {
    __shared__ float sh[512];
    int i = threadIdx.x;
    float v = 0.0f;
    for (int j = i; j < B; j += 512) v += g_res[j];
    sh[i] = v;
    __syncthreads();
#pragma unroll
    for (int s = 256; s > 0; s >>= 1) {
        if (i < s) sh[i] += sh[i + s];
        __syncthreads();
    }
    if (i == 0) out[0] = sh[0] / (float)B;
}

extern "C" void kernel_launch(void* const* d_in, const int* in_sizes, int n_in,
                              void* d_out, int out_size) {
    const float* emis    = (const float*)d_in[0];
    const int*   lengths = (const int*)d_in[1];
    const int*   tags    = (const int*)d_in[2];
    const float* prior   = (const float*)d_in[3];
    const float* trans   = (const float*)d_in[4];
    const float* ftrans  = (const float*)d_in[5];

    const int B = in_sizes[1];              // lengths count
    const int T = in_sizes[2] / B;          // tags = [B, T]

    crf_forward<<<B / 2, KTAGS>>>(emis, lengths, tags, prior, trans, ftrans, T);
    crf_reduce<<<1, 512>>>((float*)d_out, B);
}

// round 6
// speedup vs baseline: 2.3552x; 2.3552x over previous
#include <cuda_runtime.h>

#define KTAGS 48
#define PF 8
#define L2E 1.4426950408889634f
#define LN2 0.6931471805599453f

__device__ float g_res[4096];

__device__ __forceinline__ unsigned long long pk2(float lo, float hi) {
    unsigned long long r;
    asm("mov.b64 %0,{%1,%2};" : "=l"(r) : "f"(lo), "f"(hi));
    return r;
}
__device__ __forceinline__ void unpk2(unsigned long long v, float& a, float& b) {
    asm("mov.b64 {%0,%1},%2;" : "=f"(a), "=f"(b) : "l"(v));
}
__device__ __forceinline__ unsigned long long ffma2(unsigned long long a, unsigned long long b,
                                                    unsigned long long c) {
    unsigned long long d;
    asm("fma.rn.f32x2 %0,%1,%2,%3;" : "=l"(d) : "l"(a), "l"(b), "l"(c));
    return d;
}
__device__ __forceinline__ unsigned long long fadd2(unsigned long long a, unsigned long long b) {
    unsigned long long d;
    asm("add.rn.f32x2 %0,%1,%2;" : "=l"(d) : "l"(a), "l"(b));
    return d;
}
__device__ __forceinline__ float ex2f(float x) {
    float r; asm("ex2.approx.f32 %0,%1;" : "=f"(r) : "f"(x)); return r;
}
__device__ __forceinline__ float lg2f(float x) {
    float r; asm("lg2.approx.f32 %0,%1;" : "=f"(r) : "f"(x)); return r;
}
__device__ __forceinline__ float rcpf(float x) {
    float r; asm("rcp.approx.f32 %0,%1;" : "=f"(r) : "f"(x)); return r;
}

// SINGLE-WARP block per batch element. Lane j owns row j; lanes 0-15 also own
// row 32+j. Per-step sync is __syncwarp (WARPSYNC ~23cyc) instead of a
// 2-warp BAR — removes barrier skew + deferred-block cost from the chain.
// Linear-domain recursion: w = (E w) * exp(emis) / r, r = w0(stale);
// log-scale off-chain via C2 += lg2(r).
__global__ void __launch_bounds__(32) crf_forward(
    const float* __restrict__ emis,   // [B, T, K] f32
    const int* __restrict__ lengths,  // [B] i32
    const int* __restrict__ tags,     // [B, T] i32
    const float* __restrict__ prior,  // [K]
    const float* __restrict__ trans,  // [K, K]  trans[i*K+j] = score(j -> i)
    const float* __restrict__ ftrans, // [K]
    int T)
{
    __shared__ __align__(16) float sv[2][KTAGS];
    __shared__ float red[KTAGS];

    const int b = blockIdx.x;
    const int j = threadIdx.x;       // 0..31
    const bool hasB = (j < 16);
    const int rA = j;
    const int rB = 32 + (j & 15);    // valid row index even for lanes >=16 (unused)

    int L = lengths[b];
    if (L < 1) L = 1;
    if (L > T) L = T;

    const float* eb = emis + (size_t)b * T * KTAGS;

    // E rows for rA and rB, packed as f32x2.
    unsigned long long EA[24], EB[24];
    {
        const float4* trA = (const float4*)(trans + rA * KTAGS);
        const float4* trB = (const float4*)(trans + rB * KTAGS);
#pragma unroll
        for (int q = 0; q < 12; q++) {
            float4 va = trA[q];
            EA[2 * q]     = pk2(ex2f(va.x * L2E), ex2f(va.y * L2E));
            EA[2 * q + 1] = pk2(ex2f(va.z * L2E), ex2f(va.w * L2E));
            float4 vb = trB[q];
            EB[2 * q]     = pk2(ex2f(vb.x * L2E), ex2f(vb.y * L2E));
            EB[2 * q + 1] = pk2(ex2f(vb.z * L2E), ex2f(vb.w * L2E));
        }
    }

    // t = 0 init.
    float aA = eb[rA] + prior[rA];
    float aB = eb[rB] + prior[rB];
    red[rA] = aA;
    if (hasB) red[rB] = aB;
    __syncwarp();
    float m = red[0];
    float C2 = m * L2E;
    float wA = ex2f((aA - m) * L2E);
    float wB = ex2f((aB - m) * L2E);
    sv[0][rA] = wA;
    if (hasB) sv[0][rB] = wB;
    __syncwarp();
    int p = 0;

    // Prefetch rings (raw emissions; exp at consume time).
    float rawA[PF], rawB[PF];
#pragma unroll
    for (int d = 0; d < PF; d++) {
        int t = 1 + d;
        rawA[d] = (t < L) ? eb[(size_t)t * KTAGS + rA] : 0.0f;
        rawB[d] = (t < L && hasB) ? eb[(size_t)t * KTAGS + rB] : 0.0f;
    }

    for (int t0 = 1; t0 < L; t0 += PF) {
#pragma unroll
        for (int d = 0; d < PF; d++) {
            const int t = t0 + d;
            if (t >= L) break;

            float eetA = ex2f(rawA[d] * L2E);
            float eetB = ex2f(rawB[d] * L2E);
            {
                int tn = t + PF;
                rawA[d] = (tn < L) ? eb[(size_t)tn * KTAGS + rA] : 0.0f;
                rawB[d] = (tn < L && hasB) ? eb[(size_t)tn * KTAGS + rB] : 0.0f;
            }

            // Stale renormalizer; RCP/LG2 off the critical chain.
            float r = sv[p][0];
            float rr = rcpf(r);
            float gA = eetA * rr;
            float gB = eetB * rr;
            C2 += lg2f(r);

            const ulonglong2* vv = (const ulonglong2*)sv[p];
            unsigned long long a0 = pk2(0.0f, 0.0f), a1 = a0, a2 = a0, a3 = a0;
            unsigned long long b0 = a0, b1 = a0, b2 = a0, b3 = a0;
#pragma unroll
            for (int q = 0; q < 12; q += 2) {
                ulonglong2 x0 = vv[q];
                ulonglong2 x1 = vv[q + 1];
                a0 = ffma2(EA[2 * q],     x0.x, a0);
                b0 = ffma2(EB[2 * q],     x0.x, b0);
                a1 = ffma2(EA[2 * q + 1], x0.y, a1);
                b1 = ffma2(EB[2 * q + 1], x0.y, b1);
                a2 = ffma2(EA[2 * q + 2], x1.x, a2);
                b2 = ffma2(EB[2 * q + 2], x1.x, b2);
                a3 = ffma2(EA[2 * q + 3], x1.y, a3);
                b3 = ffma2(EB[2 * q + 3], x1.y, b3);
            }
            unsigned long long sA = fadd2(fadd2(a0, a1), fadd2(a2, a3));
            unsigned long long sB = fadd2(fadd2(b0, b1), fadd2(b2, b3));
            float alo, ahi, blo, bhi;
            unpk2(sA, alo, ahi);
            unpk2(sB, blo, bhi);
            wA = (alo + ahi) * gA;
            wB = (blo + bhi) * gB;

            const int q2 = p ^ 1;
            sv[q2][rA] = wA;
            if (hasB) sv[q2][rB] = wB;
            __syncwarp();
            p = q2;
        }
    }

    // ---- logZ ----
    red[rA] = wA * ex2f(ftrans[rA] * L2E);
    if (hasB) red[rB] = wB * ex2f(ftrans[rB] * L2E);
    __syncwarp();
    float logZ = 0.0f;
    if (j == 0) {
        float s = 0.0f;
#pragma unroll
        for (int k = 0; k < KTAGS; k++) s += red[k];
        logZ = (lg2f(s) + C2) * LN2;
    }
    __syncwarp();

    // ---- path score: lanes stride timesteps ----
    const int* tb = tags + (size_t)b * T;
    float acc = 0.0f;
    for (int t = j; t < L; t += 32) {
        int tg = min(max(tb[t], 0), KTAGS - 1);
        float tr = (t == 0) ? prior[tg]
                            : trans[tg * KTAGS + min(max(tb[t - 1], 0), KTAGS - 1)];
        acc += eb[(size_t)t * KTAGS + tg] + tr;
    }
#pragma unroll
    for (int s = 16; s > 0; s >>= 1)
        acc += __shfl_xor_sync(0xffffffffu, acc, s);
    if (j == 0) {
        float ps = acc + ftrans[min(max(tb[L - 1], 0), KTAGS - 1)];
        g_res[b] = logZ - ps;
    }
}

__global__ void crf_reduce(float* __restrict__ out, int B) {
    __shared__ float sh[512];
    int i = threadIdx.x;
    float v = 0.0f;
    for (int k = i; k < B; k += 512) v += g_res[k];
    sh[i] = v;
    __syncthreads();
#pragma unroll
    for (int s = 256; s > 0; s >>= 1) {
        if (i < s) sh[i] += sh[i + s];
        __syncthreads();
    }
    if (i == 0) out[0] = sh[0] / (float)B;
}

extern "C" void kernel_launch(void* const* d_in, const int* in_sizes, int n_in,
                              void* d_out, int out_size) {
    const float* emis    = (const float*)d_in[0];
    const int*   lengths = (const int*)d_in[1];
    const int*   tags    = (const int*)d_in[2];
    const float* prior   = (const float*)d_in[3];
    const float* trans   = (const float*)d_in[4];
    const float* ftrans  = (const float*)d_in[5];

    const int B = in_sizes[1];              // lengths count
    const int T = in_sizes[2] / B;          // tags = [B, T]

    crf_forward<<<B, 32>>>(emis, lengths, tags, prior, trans, ftrans, T);
    crf_reduce<<<1, 512>>>((float*)d_out, B);
}

// round 7
// speedup vs baseline: 2.4414x; 1.0366x over previous
#include <cuda_runtime.h>

#define KTAGS 48
#define PF 8
#define L2E 1.4426950408889634f
#define LN2 0.6931471805599453f

#define MAXB 4096
__device__ float g_wf[MAXB * KTAGS];
__device__ float g_wb[MAXB * KTAGS];
__device__ float g_c2f[MAXB];
__device__ float g_c2b[MAXB];
__device__ float g_path[MAXB];

__device__ __forceinline__ unsigned long long pk2(float lo, float hi) {
    unsigned long long r;
    asm("mov.b64 %0,{%1,%2};" : "=l"(r) : "f"(lo), "f"(hi));
    return r;
}
__device__ __forceinline__ void unpk2(unsigned long long v, float& a, float& b) {
    asm("mov.b64 {%0,%1},%2;" : "=f"(a), "=f"(b) : "l"(v));
}
__device__ __forceinline__ unsigned long long ffma2(unsigned long long a, unsigned long long b,
                                                    unsigned long long c) {
    unsigned long long d;
    asm("fma.rn.f32x2 %0,%1,%2,%3;" : "=l"(d) : "l"(a), "l"(b), "l"(c));
    return d;
}
__device__ __forceinline__ unsigned long long fadd2(unsigned long long a, unsigned long long b) {
    unsigned long long d;
    asm("add.rn.f32x2 %0,%1,%2;" : "=l"(d) : "l"(a), "l"(b));
    return d;
}
__device__ __forceinline__ float ex2f(float x) {
    float r; asm("ex2.approx.f32 %0,%1;" : "=f"(r) : "f"(x)); return r;
}
__device__ __forceinline__ float lg2f(float x) {
    float r; asm("lg2.approx.f32 %0,%1;" : "=f"(r) : "f"(x)); return r;
}
__device__ __forceinline__ float rcpf(float x) {
    float r; asm("rcp.approx.f32 %0,%1;" : "=f"(r) : "f"(x)); return r;
}

// Shared matvec step body: result rows rA/rB = (M . sv[p]) for this lane.
__device__ __forceinline__ void matvec48(const unsigned long long* MA,
                                         const unsigned long long* MB,
                                         const float* svp,
                                         float& outA, float& outB) {
    const ulonglong2* vv = (const ulonglong2*)svp;
    unsigned long long a0 = pk2(0.0f, 0.0f), a1 = a0, a2 = a0, a3 = a0;
    unsigned long long b0 = a0, b1 = a0, b2 = a0, b3 = a0;
#pragma unroll
    for (int q = 0; q < 12; q += 2) {
        ulonglong2 x0 = vv[q];
        ulonglong2 x1 = vv[q + 1];
        a0 = ffma2(MA[2 * q],     x0.x, a0);
        b0 = ffma2(MB[2 * q],     x0.x, b0);
        a1 = ffma2(MA[2 * q + 1], x0.y, a1);
        b1 = ffma2(MB[2 * q + 1], x0.y, b1);
        a2 = ffma2(MA[2 * q + 2], x1.x, a2);
        b2 = ffma2(MB[2 * q + 2], x1.x, b2);
        a3 = ffma2(MA[2 * q + 3], x1.y, a3);
        b3 = ffma2(MB[2 * q + 3], x1.y, b3);
    }
    unsigned long long sA = fadd2(fadd2(a0, a1), fadd2(a2, a3));
    unsigned long long sB = fadd2(fadd2(b0, b1), fadd2(b2, b3));
    float alo, ahi, blo, bhi;
    unpk2(sA, alo, ahi);
    unpk2(sB, blo, bhi);
    outA = alo + ahi;
    outB = blo + bhi;
}

// Bidirectional CRF: CTAs [0,B) run the forward alpha-recursion 0..m,
// CTAs [B,2B) run the backward beta-recursion L-1..m (m = L/2).
// Serial depth per CTA is halved vs a pure forward pass. Single warp per CTA;
// per-step sync = __syncwarp. Linear domain with stale renormalizer r and
// off-chain scale C2 += lg2(r).
__global__ void __launch_bounds__(32) crf_bidir(
    const float* __restrict__ emis,   // [B, T, K]
    const int* __restrict__ lengths,  // [B]
    const int* __restrict__ tags,     // [B, T]
    const float* __restrict__ prior,  // [K]
    const float* __restrict__ trans,  // [K, K]
    const float* __restrict__ ftrans, // [K]
    int B, int T)
{
    __shared__ __align__(16) float sv[2][KTAGS];
    __shared__ float red[KTAGS];

    const bool fwd = (blockIdx.x < (unsigned)B);
    const int b = fwd ? blockIdx.x : (blockIdx.x - B);
    const int j = threadIdx.x;
    const bool hasB = (j < 16);
    const int rA = j;
    const int rB = 32 + (j & 15);

    int L = lengths[b];
    if (L < 1) L = 1;
    if (L > T) L = T;
    const int m = L >> 1;

    const float* eb = emis + (size_t)b * T * KTAGS;

    if (fwd) {
        // E rows: EA[i][j] = exp(trans[rA][j])
        unsigned long long EA[24], EB[24];
        {
            const float4* trA = (const float4*)(trans + rA * KTAGS);
            const float4* trB = (const float4*)(trans + rB * KTAGS);
#pragma unroll
            for (int q = 0; q < 12; q++) {
                float4 va = trA[q];
                EA[2 * q]     = pk2(ex2f(va.x * L2E), ex2f(va.y * L2E));
                EA[2 * q + 1] = pk2(ex2f(va.z * L2E), ex2f(va.w * L2E));
                float4 vb4 = trB[q];
                EB[2 * q]     = pk2(ex2f(vb4.x * L2E), ex2f(vb4.y * L2E));
                EB[2 * q + 1] = pk2(ex2f(vb4.z * L2E), ex2f(vb4.w * L2E));
            }
        }

        // t = 0 init
        float aA = eb[rA] + prior[rA];
        float aB = eb[rB] + prior[rB];
        red[rA] = aA;
        if (hasB) red[rB] = aB;
        __syncwarp();
        float m0 = red[0];
        float C2 = m0 * L2E;
        float wA = ex2f((aA - m0) * L2E);
        float wB = ex2f((aB - m0) * L2E);
        sv[0][rA] = wA;
        if (hasB) sv[0][rB] = wB;
        __syncwarp();
        int p = 0;

        const int Lf = m + 1;   // consume t = 1..m
        float rawA[PF], rawB[PF];
#pragma unroll
        for (int d = 0; d < PF; d++) {
            int t = 1 + d;
            rawA[d] = (t < Lf) ? eb[(size_t)t * KTAGS + rA] : 0.0f;
            rawB[d] = (t < Lf && hasB) ? eb[(size_t)t * KTAGS + rB] : 0.0f;
        }

        for (int t0 = 1; t0 < Lf; t0 += PF) {
#pragma unroll
            for (int d = 0; d < PF; d++) {
                const int t = t0 + d;
                if (t >= Lf) break;

                float eetA = ex2f(rawA[d] * L2E);
                float eetB = ex2f(rawB[d] * L2E);
                {
                    int tn = t + PF;
                    rawA[d] = (tn < Lf) ? eb[(size_t)tn * KTAGS + rA] : 0.0f;
                    rawB[d] = (tn < Lf && hasB) ? eb[(size_t)tn * KTAGS + rB] : 0.0f;
                }

                float r = sv[p][0];
                float rr = rcpf(r);
                C2 += lg2f(r);

                float uA, uB;
                matvec48(EA, EB, sv[p], uA, uB);
                wA = uA * (eetA * rr);
                wB = uB * (eetB * rr);

                const int q2 = p ^ 1;
                sv[q2][rA] = wA;
                if (hasB) sv[q2][rB] = wB;
                __syncwarp();
                p = q2;
            }
        }

        // Output forward half state
        g_wf[b * KTAGS + rA] = wA;
        if (hasB) g_wf[b * KTAGS + rB] = wB;
        if (j == 0) g_c2f[b] = C2;

        // ---- path score over full L ----
        const int* tb = tags + (size_t)b * T;
        float acc = 0.0f;
        for (int t = j; t < L; t += 32) {
            int tg = min(max(tb[t], 0), KTAGS - 1);
            float tr = (t == 0) ? prior[tg]
                                : trans[tg * KTAGS + min(max(tb[t - 1], 0), KTAGS - 1)];
            acc += eb[(size_t)t * KTAGS + tg] + tr;
        }
#pragma unroll
        for (int s = 16; s > 0; s >>= 1)
            acc += __shfl_xor_sync(0xffffffffu, acc, s);
        if (j == 0)
            g_path[b] = acc + ftrans[min(max(tb[L - 1], 0), KTAGS - 1)];
    } else {
        // Backward half: beta recursion with E^T.
        // EbA[i][j] = exp(trans[j][rA])  (column rA of trans)
        unsigned long long EA[24], EB[24];
#pragma unroll
        for (int q = 0; q < 24; q++) {
            int j0 = 2 * q, j1 = 2 * q + 1;
            float ta0 = trans[j0 * KTAGS + rA];
            float ta1 = trans[j1 * KTAGS + rA];
            float tb0 = trans[j0 * KTAGS + rB];
            float tb1 = trans[j1 * KTAGS + rB];
            EA[q] = pk2(ex2f(ta0 * L2E), ex2f(ta1 * L2E));
            EB[q] = pk2(ex2f(tb0 * L2E), ex2f(tb1 * L2E));
        }

        float C2 = 0.0f;
        float vbA, vbB;

        if (m == L - 1) {
            // No backward steps: beta_m = ftrans.
            vbA = ex2f(ftrans[rA] * L2E);
            vbB = ex2f(ftrans[rB] * L2E);
        } else {
            // z_{L-1} = exp(ftrans + e_{L-1})
            float zA = ex2f((ftrans[rA] + eb[(size_t)(L - 1) * KTAGS + rA]) * L2E);
            float zB = ex2f((ftrans[rB] + eb[(size_t)(L - 1) * KTAGS + rB]) * L2E);
            sv[0][rA] = zA;
            if (hasB) sv[0][rB] = zB;
            __syncwarp();
            int p = 0;

            const int nsteps = L - 1 - m;   // >= 1
            const int nfull = nsteps - 1;   // iterations that renorm+store

            // Ring over descending times: s -> t = L-2-s, consumed for s < nfull.
            float rawA[PF], rawB[PF];
#pragma unroll
            for (int d = 0; d < PF; d++) {
                int t = L - 2 - d;
                rawA[d] = (d < nfull) ? eb[(size_t)t * KTAGS + rA] : 0.0f;
                rawB[d] = (d < nfull && hasB) ? eb[(size_t)t * KTAGS + rB] : 0.0f;
            }

            for (int s0 = 0; s0 < nfull; s0 += PF) {
#pragma unroll
                for (int d = 0; d < PF; d++) {
                    const int s = s0 + d;
                    if (s >= nfull) break;
                    const int t = L - 2 - s;

                    float eetA = ex2f(rawA[d] * L2E);
                    float eetB = ex2f(rawB[d] * L2E);
                    {
                        int sn = s + PF;
                        int tn = t - PF;
                        rawA[d] = (sn < nfull) ? eb[(size_t)tn * KTAGS + rA] : 0.0f;
                        rawB[d] = (sn < nfull && hasB) ? eb[(size_t)tn * KTAGS + rB] : 0.0f;
                    }

                    float r = sv[p][0];
                    float rr = rcpf(r);
                    C2 += lg2f(r);

                    float uA, uB;
                    matvec48(EA, EB, sv[p], uA, uB);
                    zA = uA * (eetA * rr);
                    zB = uB * (eetB * rr);

                    const int q2 = p ^ 1;
                    sv[q2][rA] = zA;
                    if (hasB) sv[q2][rB] = zB;
                    __syncwarp();
                    p = q2;
                }
            }
            // Final step (t = m): matvec only, no emission/renorm.
            matvec48(EA, EB, sv[p], vbA, vbB);
        }

        g_wb[b * KTAGS + rA] = vbA;
        if (hasB) g_wb[b * KTAGS + rB] = vbB;
        if (j == 0) g_c2b[b] = C2;
    }
}

// Combine halves + mean-reduce.
__global__ void crf_reduce(float* __restrict__ out, int B) {
    __shared__ float sh[512];
    int i = threadIdx.x;
    float v = 0.0f;
    for (int b = i; b < B; b += 512) {
        float dot = 0.0f;
#pragma unroll 4
        for (int k = 0; k < KTAGS; k++)
            dot += g_wf[b * KTAGS + k] * g_wb[b * KTAGS + k];
        float logZ = (lg2f(dot) + g_c2f[b] + g_c2b[b]) * LN2;
        v += logZ - g_path[b];
    }
    sh[i] = v;
    __syncthreads();
#pragma unroll
    for (int s = 256; s > 0; s >>= 1) {
        if (i < s) sh[i] += sh[i + s];
        __syncthreads();
    }
    if (i == 0) out[0] = sh[0] / (float)B;
}

extern "C" void kernel_launch(void* const* d_in, const int* in_sizes, int n_in,
                              void* d_out, int out_size) {
    const float* emis    = (const float*)d_in[0];
    const int*   lengths = (const int*)d_in[1];
    const int*   tags    = (const int*)d_in[2];
    const float* prior   = (const float*)d_in[3];
    const float* trans   = (const float*)d_in[4];
    const float* ftrans  = (const float*)d_in[5];

    const int B = in_sizes[1];              // lengths count
    const int T = in_sizes[2] / B;          // tags = [B, T]

    crf_bidir<<<2 * B, 32>>>(emis, lengths, tags, prior, trans, ftrans, B, T);
    crf_reduce<<<1, 512>>>((float*)d_out, B);
}